// round 16
// baseline (speedup 1.0000x reference)
#include <cuda_runtime.h>
#include <cuda_fp16.h>
#include <math.h>

#define VV 3
#define CC 32
#define DD 48
#define HH 128
#define WW 160
#define HW (HH*WW)        /* 20480 */
#define DHW (DD*HW)       /* 983040 */

// ---------------------------------------------------------------------------
// Scratch
// ---------------------------------------------------------------------------
__device__ float    g_xform[2][12];
__device__ float    g_feat_t[(size_t)VV*HW*CC];  // channels-last features (fp32)
__device__ unsigned g_var2[(size_t)DHW*16];      // variance fp16, 32 halves/voxel, permuted
__device__ unsigned g_h0u[(size_t)DHW*4];        // conv0 out fp16 [D,H,W,8]
__device__ unsigned g_h1u[(size_t)DHW*4];        // conv1 out fp16 [D,H,W,8]
__device__ float    g_cost[(size_t)DHW];         // conv2 out [D,H,W] fp32
__device__ unsigned g_w0t[27*2*8*8];             // conv0 weights half2 [tap][c16][j][co]

__device__ __forceinline__ unsigned f22u(float a, float b) {
    __half2 h = __floats2half2_rn(a, b);         // low = a, high = b
    return *reinterpret_cast<unsigned*>(&h);
}

// D(16x8,f32) += A(16x16,f16) * B(16x8,f16)
__device__ __forceinline__ void mma_f16_k16(float* d, const unsigned* a, const unsigned* b) {
    asm("mma.sync.aligned.m16n8k16.row.col.f32.f16.f16.f32 "
        "{%0,%1,%2,%3}, {%4,%5,%6,%7}, {%8,%9}, {%0,%1,%2,%3};"
        : "+f"(d[0]), "+f"(d[1]), "+f"(d[2]), "+f"(d[3])
        : "r"(a[0]), "r"(a[1]), "r"(a[2]), "r"(a[3]), "r"(b[0]), "r"(b[1]));
}
// D(16x8,f32) += A(16x8,f16) * B(8x8,f16)
__device__ __forceinline__ void mma_f16_k8(float* d, const unsigned* a, unsigned b) {
    asm("mma.sync.aligned.m16n8k8.row.col.f32.f16.f16.f32 "
        "{%0,%1,%2,%3}, {%4,%5}, {%6}, {%0,%1,%2,%3};"
        : "+f"(d[0]), "+f"(d[1]), "+f"(d[2]), "+f"(d[3])
        : "r"(a[0]), "r"(a[1]), "r"(b));
}

// ---------------------------------------------------------------------------
// Kernel 1: fused prep. Blocks 0..13: bake conv0 weights to half2.
// Last block, thread 0: projective transforms M_v = C_v * inv(C_0).
// ---------------------------------------------------------------------------
__global__ void k_prep(const float* __restrict__ proj, const float* __restrict__ w0) {
    if (blockIdx.x < 14) {
        int i = blockIdx.x*256 + threadIdx.x;
        if (i >= 27*2*8*8) return;
        int co  = i & 7;
        int j   = (i >> 3) & 7;
        int c16 = (i >> 6) & 1;
        int tap = i >> 7;
        int cin = c16*16 + 2*j;
        g_w0t[i] = f22u(w0[(co*32 + cin)*27 + tap], w0[(co*32 + cin + 1)*27 + tap]);
        return;
    }
    if (threadIdx.x) return;
    double Cm[3][4][4];
    for (int v = 0; v < 3; ++v) {
        double K[3][3], E[4][4];
        for (int i = 0; i < 3; ++i)
            for (int j = 0; j < 3; ++j)
                K[i][j] = (double)proj[((v*2+1)*4+i)*4+j];
        for (int i = 0; i < 4; ++i)
            for (int j = 0; j < 4; ++j)
                E[i][j] = (double)proj[((v*2+0)*4+i)*4+j];
        for (int i = 0; i < 3; ++i)
            for (int j = 0; j < 4; ++j) {
                double s = 0.0;
                for (int k = 0; k < 3; ++k) s += K[i][k]*E[k][j];
                Cm[v][i][j] = s;
            }
        for (int j = 0; j < 4; ++j) Cm[v][3][j] = E[3][j];
    }
    double A[4][8];
    for (int i = 0; i < 4; ++i)
        for (int j = 0; j < 4; ++j) { A[i][j] = Cm[0][i][j]; A[i][4+j] = (i==j) ? 1.0 : 0.0; }
    for (int col = 0; col < 4; ++col) {
        int piv = col;
        for (int r = col+1; r < 4; ++r) if (fabs(A[r][col]) > fabs(A[piv][col])) piv = r;
        if (piv != col)
            for (int j = 0; j < 8; ++j) { double t = A[col][j]; A[col][j] = A[piv][j]; A[piv][j] = t; }
        double iv = 1.0 / A[col][col];
        for (int j = 0; j < 8; ++j) A[col][j] *= iv;
        for (int r = 0; r < 4; ++r) if (r != col) {
            double f = A[r][col];
            for (int j = 0; j < 8; ++j) A[r][j] -= f * A[col][j];
        }
    }
    for (int v = 1; v < 3; ++v) {
        double M[3][4];
        for (int i = 0; i < 3; ++i)
            for (int j = 0; j < 4; ++j) {
                double s = 0.0;
                for (int k = 0; k < 4; ++k) s += Cm[v][i][k] * A[k][4+j];
                M[i][j] = s;
            }
        float* o = g_xform[v-1];
        o[0]=(float)M[0][0]; o[1]=(float)M[0][1]; o[2]=(float)M[0][2];
        o[3]=(float)M[1][0]; o[4]=(float)M[1][1]; o[5]=(float)M[1][2];
        o[6]=(float)M[2][0]; o[7]=(float)M[2][1]; o[8]=(float)M[2][2];
        o[9]=(float)M[0][3]; o[10]=(float)M[1][3]; o[11]=(float)M[2][3];
    }
}

// ---------------------------------------------------------------------------
// Kernel 2: tiled transpose [V,C,H,W] -> [V,H,W,C]
// ---------------------------------------------------------------------------
__global__ void k_transpose(const float* __restrict__ f) {
    __shared__ float t[32][33];
    int v   = blockIdx.y;
    int hw0 = blockIdx.x * 32;
    for (int i = threadIdx.y; i < 32; i += 8)
        t[i][threadIdx.x] = f[((size_t)v*32 + i)*HW + hw0 + threadIdx.x];
    __syncthreads();
    for (int i = threadIdx.y; i < 32; i += 8)
        g_feat_t[((size_t)v*HW + hw0 + i)*32 + threadIdx.x] = t[threadIdx.x][i];
}

// ---------------------------------------------------------------------------
// Kernel 3: warp+variance (round-12 body, launch_bounds(256,5)).
// ---------------------------------------------------------------------------
__global__ void __launch_bounds__(256, 5) k_warpvar(const float* __restrict__ dvals) {
    __shared__ float2 s_ow[256*9];

    const int tid   = threadIdx.x;
    const int p0    = blockIdx.x * 32;
    const int dbase = blockIdx.y * 16;
    const int g     = tid & 7;
    const int slot  = tid >> 3;
    const int px    = p0 + slot;

    const int p1p = p0 + (tid & 31);
    const float p1x = (float)(p1p % WW);
    const float p1y = (float)(p1p / WW);

    float rot[2][3];
    #pragma unroll
    for (int v = 0; v < 2; ++v) {
        const float* xf = g_xform[v];
        rot[v][0] = xf[0]*p1x + xf[1]*p1y + xf[2];
        rot[v][1] = xf[3]*p1x + xf[4]*p1y + xf[5];
        rot[v][2] = xf[6]*p1x + xf[7]*p1y + xf[8];
    }

    const float4 r = *(const float4*)(g_feat_t + (size_t)px*CC + g*4);
    const float rqx = r.x*r.x, rqy = r.y*r.y, rqz = r.z*r.z, rqw = r.w*r.w;

    const float* s1 = g_feat_t + (size_t)HW*CC;
    const float* s2 = g_feat_t + (size_t)2*HW*CC;

    #pragma unroll
    for (int dc = 0; dc < 2; ++dc) {
        {
            int d = dbase + dc*8 + (tid >> 5);
            float depth = dvals[d*HW + p1p];
            #pragma unroll
            for (int v = 0; v < 2; ++v) {
                const float* xf = g_xform[v];
                float pxx = rot[v][0]*depth + xf[9];
                float pyy = rot[v][1]*depth + xf[10];
                float pzz = rot[v][2]*depth + xf[11];
                float gx = pxx / pzz / ((float)(WW-1)*0.5f) - 1.0f;
                float gy = pyy / pzz / ((float)(HH-1)*0.5f) - 1.0f;
                float sx = (gx + 1.0f) * 0.5f * (float)(WW-1);
                float sy = (gy + 1.0f) * 0.5f * (float)(HH-1);
                float x0 = floorf(sx), y0 = floorf(sy);
                float wx1 = sx - x0, wx0 = 1.0f - wx1;
                float wy1 = sy - y0, wy0 = 1.0f - wy1;
                float cx[2] = {x0, x0+1.0f}, cy[2] = {y0, y0+1.0f};
                float wx[2] = {wx0, wx1}, wy[2] = {wy0, wy1};
                #pragma unroll
                for (int cyi = 0; cyi < 2; ++cyi)
                #pragma unroll
                for (int cxi = 0; cxi < 2; ++cxi) {
                    float xi = cx[cxi], yi = cy[cyi];
                    bool valid = (xi >= 0.0f) && (xi <= (float)(WW-1)) &&
                                 (yi >= 0.0f) && (yi <= (float)(HH-1));
                    float xc = fminf(fmaxf(xi, 0.0f), (float)(WW-1));
                    float yc = fminf(fmaxf(yi, 0.0f), (float)(HH-1));
                    int ii = (int)yc * WW + (int)xc;
                    float wgt = wx[cxi]*wy[cyi] * (valid ? 1.0f : 0.0f);
                    s_ow[tid*9 + v*4 + cyi*2 + cxi] =
                        make_float2(__int_as_float(ii * CC), wgt);
                }
            }
        }
        __syncthreads();

        #pragma unroll 1
        for (int pass = 0; pass < 8; ++pass) {
            int j   = pass*32 + slot;
            int d   = dbase + dc*8 + pass;
            int idx = d*HW + px;
            const float2* mw = s_ow + j*9;

            float sx_ = r.x, sy_ = r.y, sz_ = r.z, sw_ = r.w;
            float qx = rqx, qy = rqy, qz = rqz, qw = rqw;
            #pragma unroll
            for (int v = 0; v < 2; ++v) {
                const float* base = (v == 0) ? s1 : s2;
                float wxp = 0.f, wyp = 0.f, wzp = 0.f, wwp = 0.f;
                #pragma unroll
                for (int k = 0; k < 4; ++k) {
                    float2 ow = mw[v*4 + k];
                    float cw = ow.y;
                    const float4 f = *(const float4*)(base + __float_as_int(ow.x) + g*4);
                    wxp = fmaf(cw, f.x, wxp);
                    wyp = fmaf(cw, f.y, wyp);
                    wzp = fmaf(cw, f.z, wzp);
                    wwp = fmaf(cw, f.w, wwp);
                }
                sx_ += wxp; sy_ += wyp; sz_ += wzp; sw_ += wwp;
                qx = fmaf(wxp, wxp, qx); qy = fmaf(wyp, wyp, qy);
                qz = fmaf(wzp, wzp, qz); qw = fmaf(wwp, wwp, qw);
            }
            float mx = sx_ / 3.0f, my = sy_ / 3.0f, mz = sz_ / 3.0f, mw2 = sw_ / 3.0f;
            unsigned u0 = f22u(qx/3.0f - mx*mx, qy/3.0f - my*my);
            unsigned u1 = f22u(qz/3.0f - mz*mz, qw/3.0f - mw2*mw2);
            unsigned send = (g & 2) ? u0 : u1;
            unsigned recv = __shfl_xor_sync(0xffffffffu, send, 2);
            uint2 ov = (g & 2) ? make_uint2(recv, u1) : make_uint2(u0, recv);
            int pairidx = ((g & 1) << 1) | ((g >> 1) & 1);
            *(uint2*)(g_var2 + (size_t)idx*16 + (g >> 2)*8 + pairidx*2) = ov;
        }
        __syncthreads();
    }
}

// ---------------------------------------------------------------------------
// Kernel 4: conv0 (32->8) fp16 m16n8k16. DS=6, NSL=8, slab+smem weights
// (106KB -> still 2 CTAs/SM). Mainloop B-fragments from conflict-free LDS.
// ---------------------------------------------------------------------------
__global__ void __launch_bounds__(256, 2)
k_conv0(const float* __restrict__ wgt, const float* __restrict__ bias) {
    constexpr int DS = 6, NSL = 8;
    constexpr int SLICEU = 180*16;                // 2880 uint units per slice
    constexpr int WSZ = 27*2*64;                  // 3456 weight units

    extern __shared__ unsigned smu[];
    unsigned* s_w  = smu;                         // [tap][c16][j][co]
    unsigned* slab = smu + WSZ;

    const int tid  = threadIdx.x;
    const int ty   = tid >> 5;
    const int lane = tid & 31;
    const int gid  = lane >> 2;
    const int tig  = lane & 3;
    const int w0 = blockIdx.x * 16;
    const int h0 = blockIdx.y * 8;
    const int d0 = blockIdx.z * DS;

    // stage weights into smem (one pass)
    for (int i = tid; i < WSZ; i += 256)
        s_w[i] = g_w0t[i];

    {
        const int NTOT = NSL*180*4;
        for (int i = tid; i < NTOT; i += 256) {
            int q16 = i & 3;
            int col = (i >> 2) % 18;
            int rem = i / 72;
            int row = rem % 10;
            int s   = rem / 10;
            int z  = d0 - 1 + s;
            int gh = h0 - 1 + row;
            int gw = w0 - 1 + col;
            uint4 v = make_uint4(0,0,0,0);
            if (z >= 0 && z < DD && gh >= 0 && gh < HH && gw >= 0 && gw < WW)
                v = *(const uint4*)(g_var2 + ((size_t)(z*HH + gh)*WW + gw)*16 + q16*4);
            int pix = row*18 + col;
            int e2  = ((pix >> 1) & 1) << 1;
            *(uint4*)(slab + s*SLICEU + pix*16 + (q16 ^ e2)*4) = v;
        }
    }
    __syncthreads();

    float acc[DS][4];
    #pragma unroll
    for (int o = 0; o < DS; ++o)
        #pragma unroll
        for (int j = 0; j < 4; ++j) acc[o][j] = 0.f;

    const unsigned* wthr = s_w + tig*8 + gid;     // per-thread weight base

    #pragma unroll 1
    for (int kh = 0; kh < 3; ++kh) {
        #pragma unroll
        for (int kw = 0; kw < 3; ++kw) {
            const int tap9 = kh*3 + kw;
            const int p_lo = (ty + kh)*18 + kw + gid;
            const int e    = (p_lo >> 1) & 1;
            const unsigned* plo = slab + p_lo*16 + 2*tig;
            const unsigned* phi = plo + 128;
            #pragma unroll
            for (int c16 = 0; c16 < 2; ++c16) {
                const int co8 = (c16 ^ e) * 8;
                unsigned a[NSL][4];
                #pragma unroll
                for (int s = 0; s < NSL; ++s) {
                    uint2 lo = *(const uint2*)(plo + s*SLICEU + co8);
                    uint2 hi = *(const uint2*)(phi + s*SLICEU + co8);
                    a[s][0] = lo.x; a[s][1] = hi.x;
                    a[s][2] = lo.y; a[s][3] = hi.y;
                }
                unsigned b[3][2];
                #pragma unroll
                for (int kd = 0; kd < 3; ++kd) {
                    const unsigned* wp = wthr + ((kd*9 + tap9)*2 + c16)*64;
                    b[kd][0] = wp[0];
                    b[kd][1] = wp[32];
                }
                #pragma unroll
                for (int kd = 0; kd < 3; ++kd)
                    #pragma unroll
                    for (int o = 0; o < DS; ++o)
                        mma_f16_k16(acc[o], a[o+kd], b[kd]);
            }
        }
    }

    const float b0f = bias[2*tig], b1f = bias[2*tig+1];
    #pragma unroll
    for (int o = 0; o < DS; ++o) {
        int d = d0 + o;
        unsigned* rowp = g_h0u + ((size_t)(d*HH + h0+ty)*WW + w0)*4 + tig;
        unsigned v0 = f22u(fmaxf(acc[o][0] + b0f, 0.f), fmaxf(acc[o][1] + b1f, 0.f));
        unsigned v1 = f22u(fmaxf(acc[o][2] + b0f, 0.f), fmaxf(acc[o][3] + b1f, 0.f));
        rowp[gid*4]     = v0;
        rowp[(gid+8)*4] = v1;
    }
}

// ---------------------------------------------------------------------------
// Kernels 5-6: conv1 (8->8) / conv2 (8->1), fp16, launch_bounds(256,4).
// ---------------------------------------------------------------------------
template<int STAGE>
__global__ void __launch_bounds__(256, 4)
k_conv(const float* __restrict__ wgt, const float* __restrict__ bias) {
    constexpr int DS = 6, NSL = 8;
    constexpr int SLICEU = 180*4;

    const unsigned* __restrict__ xin = (STAGE == 1) ? g_h0u : g_h1u;

    extern __shared__ unsigned smu[];
    unsigned* s_w  = smu;                         // 864: [tap9][kd][j4][co8]
    unsigned* slab = smu + 864;

    const int tid  = threadIdx.x;
    const int ty   = tid >> 5;
    const int lane = tid & 31;
    const int gid  = lane >> 2;
    const int tig  = lane & 3;
    const int w0 = blockIdx.x * 16;
    const int h0 = blockIdx.y * 8;
    const int d0 = blockIdx.z * DS;

    for (int i = tid; i < 864; i += 256) {
        int co    = i & 7;
        int j     = (i >> 3) & 3;
        int kdtap = i >> 5;
        int kd    = kdtap % 3;
        int tap9  = kdtap / 3;
        int cin   = 2*j;
        int tap   = kd*9 + tap9;
        unsigned val;
        if (STAGE == 1)
            val = f22u(wgt[(co*8 + cin)*27 + tap], wgt[(co*8 + cin + 1)*27 + tap]);
        else
            val = (co == 0) ? f22u(wgt[cin*27 + tap], wgt[(cin+1)*27 + tap]) : 0u;
        s_w[i] = val;
    }
    {
        const int NTOT = NSL*180;
        for (int i = tid; i < NTOT; i += 256) {
            int col = i % 18;
            int row = (i / 18) % 10;
            int s   = i / 180;
            int z  = d0 - 1 + s;
            int gh = h0 - 1 + row;
            int gw = w0 - 1 + col;
            uint4 v = make_uint4(0,0,0,0);
            if (z >= 0 && z < DD && gh >= 0 && gh < HH && gw >= 0 && gw < WW)
                v = *(const uint4*)(xin + ((size_t)(z*HH + gh)*WW + gw)*4);
            *(uint4*)(slab + s*SLICEU + (row*18 + col)*4) = v;
        }
    }
    __syncthreads();

    float acc[DS][4];
    #pragma unroll
    for (int o = 0; o < DS; ++o)
        #pragma unroll
        for (int j = 0; j < 4; ++j) acc[o][j] = 0.f;

    #pragma unroll 1
    for (int kh = 0; kh < 3; ++kh) {
        #pragma unroll
        for (int kw = 0; kw < 3; ++kw) {
            const int p_lo = (ty + kh)*18 + kw + gid;
            const unsigned* plo = slab + p_lo*4 + tig;
            const unsigned* phi = plo + 32;
            unsigned alo[NSL], ahi[NSL];
            #pragma unroll
            for (int s = 0; s < NSL; ++s) {
                alo[s] = plo[s*SLICEU];
                ahi[s] = phi[s*SLICEU];
            }
            const unsigned* wb = s_w + (kh*3 + kw)*96;
            unsigned b0 = wb[tig*8 + gid];
            unsigned b1 = wb[32 + tig*8 + gid];
            unsigned b2 = wb[64 + tig*8 + gid];
            unsigned b01[2] = {b0, b1};
            #pragma unroll
            for (int o = 0; o < DS; ++o) {
                unsigned a16[4] = {alo[o], ahi[o], alo[o+1], ahi[o+1]};
                mma_f16_k16(acc[o], a16, b01);
                unsigned a8[2] = {alo[o+2], ahi[o+2]};
                mma_f16_k8(acc[o], a8, b2);
            }
        }
    }

    if (STAGE == 1) {
        const float b0f = bias[2*tig], b1f = bias[2*tig+1];
        #pragma unroll
        for (int o = 0; o < DS; ++o) {
            int d = d0 + o;
            unsigned* rowp = g_h1u + ((size_t)(d*HH + h0+ty)*WW + w0)*4 + tig;
            unsigned v0 = f22u(fmaxf(acc[o][0] + b0f, 0.f), fmaxf(acc[o][1] + b1f, 0.f));
            unsigned v1 = f22u(fmaxf(acc[o][2] + b0f, 0.f), fmaxf(acc[o][3] + b1f, 0.f));
            rowp[gid*4]     = v0;
            rowp[(gid+8)*4] = v1;
        }
    } else {
        const float b0f = bias[0];
        if (tig == 0) {
            #pragma unroll
            for (int o = 0; o < DS; ++o) {
                int d = d0 + o;
                float* row = g_cost + (size_t)(d*HH + h0+ty)*WW + w0;
                row[gid]   = acc[o][0] + b0f;
                row[gid+8] = acc[o][2] + b0f;
            }
        }
    }
}

// ---------------------------------------------------------------------------
// Kernel 7: softmax over D + expected depth + 4-tap confidence
// ---------------------------------------------------------------------------
__global__ void k_softmax(const float* __restrict__ dvals, float* __restrict__ out) {
    int p = blockIdx.x*blockDim.x + threadIdx.x;
    if (p >= HW) return;
    float c[DD];
    float m = -1e30f;
    #pragma unroll
    for (int d = 0; d < DD; ++d) { c[d] = g_cost[(size_t)d*HW + p]; m = fmaxf(m, c[d]); }
    float S = 0.f;
    #pragma unroll
    for (int d = 0; d < DD; ++d) { c[d] = expf(c[d] - m); S += c[d]; }
    float inv = 1.0f / S;
    float depth = 0.f, fid = 0.f;
    #pragma unroll
    for (int d = 0; d < DD; ++d) {
        float pr = c[d] * inv;
        depth = fmaf(pr, dvals[(size_t)d*HW + p], depth);
        fid   = fmaf(pr, (float)d, fid);
    }
    int di = (int)fid;
    di = max(0, min(DD-1, di));
    float conf = 0.f;
    #pragma unroll
    for (int d = 0; d < DD; ++d)
        if (d >= di-1 && d <= di+2) conf += c[d] * inv;
    out[p]      = depth;
    out[HW + p] = conf;
}

// ---------------------------------------------------------------------------
// Launch
// ---------------------------------------------------------------------------
extern "C" void kernel_launch(void* const* d_in, const int* in_sizes, int n_in,
                              void* d_out, int out_size) {
    const float* features = (const float*)d_in[0];
    const float* proj     = (const float*)d_in[1];
    const float* dvals    = (const float*)d_in[2];
    const float* w0 = (const float*)d_in[3];
    const float* b0 = (const float*)d_in[4];
    const float* w1 = (const float*)d_in[5];
    const float* b1 = (const float*)d_in[6];
    const float* w2 = (const float*)d_in[7];
    const float* b2 = (const float*)d_in[8];
    float* out = (float*)d_out;

    const int smem0  = (27*2*64 + 8*2880)*4;     // 13824 + 92160 = 105984 B
    const int smem12 = (864 + 8*720)*4;          // 26496 B
    cudaFuncSetAttribute(k_conv0,   cudaFuncAttributeMaxDynamicSharedMemorySize, smem0);
    cudaFuncSetAttribute(k_conv<1>, cudaFuncAttributeMaxDynamicSharedMemorySize, smem12);
    cudaFuncSetAttribute(k_conv<2>, cudaFuncAttributeMaxDynamicSharedMemorySize, smem12);

    k_prep<<<15, 256>>>(proj, w0);
    dim3 tgrid(HW/32, VV);
    k_transpose<<<tgrid, dim3(32, 8)>>>(features);
    dim3 wgrid(HW/32, 3);
    k_warpvar<<<wgrid, 256>>>(dvals);

    dim3 cgrid(WW/16, HH/8, DD/6);   // (10, 16, 8)
    k_conv0<<<cgrid, 256, smem0>>>(w0, b0);
    k_conv<1><<<cgrid, 256, smem12>>>(w1, b1);
    k_conv<2><<<cgrid, 256, smem12>>>(w2, b2);

    k_softmax<<<(HW + 255)/256, 256>>>(dvals, out);
}

// round 17
// speedup vs baseline: 1.0444x; 1.0444x over previous
#include <cuda_runtime.h>
#include <cuda_fp16.h>
#include <math.h>

#define VV 3
#define CC 32
#define DD 48
#define HH 128
#define WW 160
#define HW (HH*WW)        /* 20480 */
#define DHW (DD*HW)       /* 983040 */

// ---------------------------------------------------------------------------
// Scratch
// ---------------------------------------------------------------------------
__device__ float    g_xform[2][12];
__device__ float    g_feat_t[(size_t)VV*HW*CC];  // channels-last features (fp32)
__device__ unsigned g_var2[(size_t)DHW*16];      // variance fp16, 32 halves/voxel, permuted
__device__ unsigned g_h0u[(size_t)DHW*4];        // conv0 out fp16 [D,H,W,8]
__device__ unsigned g_h1u[(size_t)DHW*4];        // conv1 out fp16 [D,H,W,8]
__device__ float    g_cost[(size_t)DHW];         // conv2 out [D,H,W] fp32
__device__ unsigned g_w0t[27*2*8*8];             // conv0 weights half2 [tap][c16][j][co]

__device__ __forceinline__ unsigned f22u(float a, float b) {
    __half2 h = __floats2half2_rn(a, b);         // low = a, high = b
    return *reinterpret_cast<unsigned*>(&h);
}

// D(16x8,f32) += A(16x16,f16) * B(16x8,f16)
__device__ __forceinline__ void mma_f16_k16(float* d, const unsigned* a, const unsigned* b) {
    asm("mma.sync.aligned.m16n8k16.row.col.f32.f16.f16.f32 "
        "{%0,%1,%2,%3}, {%4,%5,%6,%7}, {%8,%9}, {%0,%1,%2,%3};"
        : "+f"(d[0]), "+f"(d[1]), "+f"(d[2]), "+f"(d[3])
        : "r"(a[0]), "r"(a[1]), "r"(a[2]), "r"(a[3]), "r"(b[0]), "r"(b[1]));
}
// D(16x8,f32) += A(16x8,f16) * B(8x8,f16)
__device__ __forceinline__ void mma_f16_k8(float* d, const unsigned* a, unsigned b) {
    asm("mma.sync.aligned.m16n8k8.row.col.f32.f16.f16.f32 "
        "{%0,%1,%2,%3}, {%4,%5}, {%6}, {%0,%1,%2,%3};"
        : "+f"(d[0]), "+f"(d[1]), "+f"(d[2]), "+f"(d[3])
        : "r"(a[0]), "r"(a[1]), "r"(b));
}

// ---------------------------------------------------------------------------
// Kernel 1: fused prep. Blocks 0..13: bake conv0 weights to half2.
// Last block, thread 0: projective transforms M_v = C_v * inv(C_0).
// ---------------------------------------------------------------------------
__global__ void k_prep(const float* __restrict__ proj, const float* __restrict__ w0) {
    if (blockIdx.x < 14) {
        int i = blockIdx.x*256 + threadIdx.x;
        if (i >= 27*2*8*8) return;
        int co  = i & 7;
        int j   = (i >> 3) & 7;
        int c16 = (i >> 6) & 1;
        int tap = i >> 7;
        int cin = c16*16 + 2*j;
        g_w0t[i] = f22u(w0[(co*32 + cin)*27 + tap], w0[(co*32 + cin + 1)*27 + tap]);
        return;
    }
    if (threadIdx.x) return;
    double Cm[3][4][4];
    for (int v = 0; v < 3; ++v) {
        double K[3][3], E[4][4];
        for (int i = 0; i < 3; ++i)
            for (int j = 0; j < 3; ++j)
                K[i][j] = (double)proj[((v*2+1)*4+i)*4+j];
        for (int i = 0; i < 4; ++i)
            for (int j = 0; j < 4; ++j)
                E[i][j] = (double)proj[((v*2+0)*4+i)*4+j];
        for (int i = 0; i < 3; ++i)
            for (int j = 0; j < 4; ++j) {
                double s = 0.0;
                for (int k = 0; k < 3; ++k) s += K[i][k]*E[k][j];
                Cm[v][i][j] = s;
            }
        for (int j = 0; j < 4; ++j) Cm[v][3][j] = E[3][j];
    }
    double A[4][8];
    for (int i = 0; i < 4; ++i)
        for (int j = 0; j < 4; ++j) { A[i][j] = Cm[0][i][j]; A[i][4+j] = (i==j) ? 1.0 : 0.0; }
    for (int col = 0; col < 4; ++col) {
        int piv = col;
        for (int r = col+1; r < 4; ++r) if (fabs(A[r][col]) > fabs(A[piv][col])) piv = r;
        if (piv != col)
            for (int j = 0; j < 8; ++j) { double t = A[col][j]; A[col][j] = A[piv][j]; A[piv][j] = t; }
        double iv = 1.0 / A[col][col];
        for (int j = 0; j < 8; ++j) A[col][j] *= iv;
        for (int r = 0; r < 4; ++r) if (r != col) {
            double f = A[r][col];
            for (int j = 0; j < 8; ++j) A[r][j] -= f * A[col][j];
        }
    }
    for (int v = 1; v < 3; ++v) {
        double M[3][4];
        for (int i = 0; i < 3; ++i)
            for (int j = 0; j < 4; ++j) {
                double s = 0.0;
                for (int k = 0; k < 4; ++k) s += Cm[v][i][k] * A[k][4+j];
                M[i][j] = s;
            }
        float* o = g_xform[v-1];
        o[0]=(float)M[0][0]; o[1]=(float)M[0][1]; o[2]=(float)M[0][2];
        o[3]=(float)M[1][0]; o[4]=(float)M[1][1]; o[5]=(float)M[1][2];
        o[6]=(float)M[2][0]; o[7]=(float)M[2][1]; o[8]=(float)M[2][2];
        o[9]=(float)M[0][3]; o[10]=(float)M[1][3]; o[11]=(float)M[2][3];
    }
}

// ---------------------------------------------------------------------------
// Kernel 2: tiled transpose [V,C,H,W] -> [V,H,W,C]
// ---------------------------------------------------------------------------
__global__ void k_transpose(const float* __restrict__ f) {
    __shared__ float t[32][33];
    int v   = blockIdx.y;
    int hw0 = blockIdx.x * 32;
    for (int i = threadIdx.y; i < 32; i += 8)
        t[i][threadIdx.x] = f[((size_t)v*32 + i)*HW + hw0 + threadIdx.x];
    __syncthreads();
    for (int i = threadIdx.y; i < 32; i += 8)
        g_feat_t[((size_t)v*HW + hw0 + i)*32 + threadIdx.x] = t[threadIdx.x][i];
}

// ---------------------------------------------------------------------------
// Kernel 3: warp+variance (round-12 body, launch_bounds(256,5)).
// ---------------------------------------------------------------------------
__global__ void __launch_bounds__(256, 5) k_warpvar(const float* __restrict__ dvals) {
    __shared__ float2 s_ow[256*9];

    const int tid   = threadIdx.x;
    const int p0    = blockIdx.x * 32;
    const int dbase = blockIdx.y * 16;
    const int g     = tid & 7;
    const int slot  = tid >> 3;
    const int px    = p0 + slot;

    const int p1p = p0 + (tid & 31);
    const float p1x = (float)(p1p % WW);
    const float p1y = (float)(p1p / WW);

    float rot[2][3];
    #pragma unroll
    for (int v = 0; v < 2; ++v) {
        const float* xf = g_xform[v];
        rot[v][0] = xf[0]*p1x + xf[1]*p1y + xf[2];
        rot[v][1] = xf[3]*p1x + xf[4]*p1y + xf[5];
        rot[v][2] = xf[6]*p1x + xf[7]*p1y + xf[8];
    }

    const float4 r = *(const float4*)(g_feat_t + (size_t)px*CC + g*4);
    const float rqx = r.x*r.x, rqy = r.y*r.y, rqz = r.z*r.z, rqw = r.w*r.w;

    const float* s1 = g_feat_t + (size_t)HW*CC;
    const float* s2 = g_feat_t + (size_t)2*HW*CC;

    #pragma unroll
    for (int dc = 0; dc < 2; ++dc) {
        {
            int d = dbase + dc*8 + (tid >> 5);
            float depth = dvals[d*HW + p1p];
            #pragma unroll
            for (int v = 0; v < 2; ++v) {
                const float* xf = g_xform[v];
                float pxx = rot[v][0]*depth + xf[9];
                float pyy = rot[v][1]*depth + xf[10];
                float pzz = rot[v][2]*depth + xf[11];
                float gx = pxx / pzz / ((float)(WW-1)*0.5f) - 1.0f;
                float gy = pyy / pzz / ((float)(HH-1)*0.5f) - 1.0f;
                float sx = (gx + 1.0f) * 0.5f * (float)(WW-1);
                float sy = (gy + 1.0f) * 0.5f * (float)(HH-1);
                float x0 = floorf(sx), y0 = floorf(sy);
                float wx1 = sx - x0, wx0 = 1.0f - wx1;
                float wy1 = sy - y0, wy0 = 1.0f - wy1;
                float cx[2] = {x0, x0+1.0f}, cy[2] = {y0, y0+1.0f};
                float wx[2] = {wx0, wx1}, wy[2] = {wy0, wy1};
                #pragma unroll
                for (int cyi = 0; cyi < 2; ++cyi)
                #pragma unroll
                for (int cxi = 0; cxi < 2; ++cxi) {
                    float xi = cx[cxi], yi = cy[cyi];
                    bool valid = (xi >= 0.0f) && (xi <= (float)(WW-1)) &&
                                 (yi >= 0.0f) && (yi <= (float)(HH-1));
                    float xc = fminf(fmaxf(xi, 0.0f), (float)(WW-1));
                    float yc = fminf(fmaxf(yi, 0.0f), (float)(HH-1));
                    int ii = (int)yc * WW + (int)xc;
                    float wgt = wx[cxi]*wy[cyi] * (valid ? 1.0f : 0.0f);
                    s_ow[tid*9 + v*4 + cyi*2 + cxi] =
                        make_float2(__int_as_float(ii * CC), wgt);
                }
            }
        }
        __syncthreads();

        #pragma unroll 1
        for (int pass = 0; pass < 8; ++pass) {
            int j   = pass*32 + slot;
            int d   = dbase + dc*8 + pass;
            int idx = d*HW + px;
            const float2* mw = s_ow + j*9;

            float sx_ = r.x, sy_ = r.y, sz_ = r.z, sw_ = r.w;
            float qx = rqx, qy = rqy, qz = rqz, qw = rqw;
            #pragma unroll
            for (int v = 0; v < 2; ++v) {
                const float* base = (v == 0) ? s1 : s2;
                float wxp = 0.f, wyp = 0.f, wzp = 0.f, wwp = 0.f;
                #pragma unroll
                for (int k = 0; k < 4; ++k) {
                    float2 ow = mw[v*4 + k];
                    float cw = ow.y;
                    const float4 f = *(const float4*)(base + __float_as_int(ow.x) + g*4);
                    wxp = fmaf(cw, f.x, wxp);
                    wyp = fmaf(cw, f.y, wyp);
                    wzp = fmaf(cw, f.z, wzp);
                    wwp = fmaf(cw, f.w, wwp);
                }
                sx_ += wxp; sy_ += wyp; sz_ += wzp; sw_ += wwp;
                qx = fmaf(wxp, wxp, qx); qy = fmaf(wyp, wyp, qy);
                qz = fmaf(wzp, wzp, qz); qw = fmaf(wwp, wwp, qw);
            }
            float mx = sx_ / 3.0f, my = sy_ / 3.0f, mz = sz_ / 3.0f, mw2 = sw_ / 3.0f;
            unsigned u0 = f22u(qx/3.0f - mx*mx, qy/3.0f - my*my);
            unsigned u1 = f22u(qz/3.0f - mz*mz, qw/3.0f - mw2*mw2);
            unsigned send = (g & 2) ? u0 : u1;
            unsigned recv = __shfl_xor_sync(0xffffffffu, send, 2);
            uint2 ov = (g & 2) ? make_uint2(recv, u1) : make_uint2(u0, recv);
            int pairidx = ((g & 1) << 1) | ((g >> 1) & 1);
            *(uint2*)(g_var2 + (size_t)idx*16 + (g >> 2)*8 + pairidx*2) = ov;
        }
        __syncthreads();
    }
}

// ---------------------------------------------------------------------------
// Kernel 4: conv0 (32->8) fp16 m16n8k16. DS=6, NSL=8, slab 92KB, 2 CTAs/SM,
// B-fragments from gmem (proven round-15 71us configuration).
// ---------------------------------------------------------------------------
__global__ void __launch_bounds__(256, 2)
k_conv0(const float* __restrict__ wgt, const float* __restrict__ bias) {
    constexpr int DS = 6, NSL = 8;
    constexpr int SLICEU = 180*16;                // 2880 uint units per slice

    extern __shared__ unsigned smu[];             // slab only

    const int tid  = threadIdx.x;
    const int ty   = tid >> 5;
    const int lane = tid & 31;
    const int gid  = lane >> 2;
    const int tig  = lane & 3;
    const int w0 = blockIdx.x * 16;
    const int h0 = blockIdx.y * 8;
    const int d0 = blockIdx.z * DS;

    {
        const int NTOT = NSL*180*4;
        for (int i = tid; i < NTOT; i += 256) {
            int q16 = i & 3;
            int col = (i >> 2) % 18;
            int rem = i / 72;
            int row = rem % 10;
            int s   = rem / 10;
            int z  = d0 - 1 + s;
            int gh = h0 - 1 + row;
            int gw = w0 - 1 + col;
            uint4 v = make_uint4(0,0,0,0);
            if (z >= 0 && z < DD && gh >= 0 && gh < HH && gw >= 0 && gw < WW)
                v = *(const uint4*)(g_var2 + ((size_t)(z*HH + gh)*WW + gw)*16 + q16*4);
            int pix = row*18 + col;
            int e2  = ((pix >> 1) & 1) << 1;
            *(uint4*)(smu + s*SLICEU + pix*16 + (q16 ^ e2)*4) = v;
        }
    }
    __syncthreads();

    float acc[DS][4];
    #pragma unroll
    for (int o = 0; o < DS; ++o)
        #pragma unroll
        for (int j = 0; j < 4; ++j) acc[o][j] = 0.f;

    #pragma unroll 1
    for (int kh = 0; kh < 3; ++kh) {
        #pragma unroll
        for (int kw = 0; kw < 3; ++kw) {
            const int tap9 = kh*3 + kw;
            const int p_lo = (ty + kh)*18 + kw + gid;
            const int e    = (p_lo >> 1) & 1;
            const unsigned* plo = smu + p_lo*16 + 2*tig;
            const unsigned* phi = plo + 128;
            #pragma unroll
            for (int c16 = 0; c16 < 2; ++c16) {
                const int co8 = (c16 ^ e) * 8;
                unsigned a[NSL][4];
                #pragma unroll
                for (int s = 0; s < NSL; ++s) {
                    uint2 lo = *(const uint2*)(plo + s*SLICEU + co8);
                    uint2 hi = *(const uint2*)(phi + s*SLICEU + co8);
                    a[s][0] = lo.x; a[s][1] = hi.x;
                    a[s][2] = lo.y; a[s][3] = hi.y;
                }
                unsigned b[3][2];
                #pragma unroll
                for (int kd = 0; kd < 3; ++kd) {
                    const unsigned* wp = g_w0t + ((kd*9 + tap9)*2 + c16)*64 + tig*8 + gid;
                    b[kd][0] = wp[0];
                    b[kd][1] = wp[32];
                }
                #pragma unroll
                for (int kd = 0; kd < 3; ++kd)
                    #pragma unroll
                    for (int o = 0; o < DS; ++o)
                        mma_f16_k16(acc[o], a[o+kd], b[kd]);
            }
        }
    }

    const float b0f = bias[2*tig], b1f = bias[2*tig+1];
    #pragma unroll
    for (int o = 0; o < DS; ++o) {
        int d = d0 + o;
        unsigned* rowp = g_h0u + ((size_t)(d*HH + h0+ty)*WW + w0)*4 + tig;
        unsigned v0 = f22u(fmaxf(acc[o][0] + b0f, 0.f), fmaxf(acc[o][1] + b1f, 0.f));
        unsigned v1 = f22u(fmaxf(acc[o][2] + b0f, 0.f), fmaxf(acc[o][3] + b1f, 0.f));
        rowp[gid*4]     = v0;
        rowp[(gid+8)*4] = v1;
    }
}

// ---------------------------------------------------------------------------
// Kernels 5-6: conv1 (8->8) / conv2 (8->1), fp16, launch_bounds(256,4).
// ---------------------------------------------------------------------------
template<int STAGE>
__global__ void __launch_bounds__(256, 4)
k_conv(const float* __restrict__ wgt, const float* __restrict__ bias) {
    constexpr int DS = 6, NSL = 8;
    constexpr int SLICEU = 180*4;

    const unsigned* __restrict__ xin = (STAGE == 1) ? g_h0u : g_h1u;

    extern __shared__ unsigned smu[];
    unsigned* s_w  = smu;                         // 864: [tap9][kd][j4][co8]
    unsigned* slab = smu + 864;

    const int tid  = threadIdx.x;
    const int ty   = tid >> 5;
    const int lane = tid & 31;
    const int gid  = lane >> 2;
    const int tig  = lane & 3;
    const int w0 = blockIdx.x * 16;
    const int h0 = blockIdx.y * 8;
    const int d0 = blockIdx.z * DS;

    for (int i = tid; i < 864; i += 256) {
        int co    = i & 7;
        int j     = (i >> 3) & 3;
        int kdtap = i >> 5;
        int kd    = kdtap % 3;
        int tap9  = kdtap / 3;
        int cin   = 2*j;
        int tap   = kd*9 + tap9;
        unsigned val;
        if (STAGE == 1)
            val = f22u(wgt[(co*8 + cin)*27 + tap], wgt[(co*8 + cin + 1)*27 + tap]);
        else
            val = (co == 0) ? f22u(wgt[cin*27 + tap], wgt[(cin+1)*27 + tap]) : 0u;
        s_w[i] = val;
    }
    {
        const int NTOT = NSL*180;
        for (int i = tid; i < NTOT; i += 256) {
            int col = i % 18;
            int row = (i / 18) % 10;
            int s   = i / 180;
            int z  = d0 - 1 + s;
            int gh = h0 - 1 + row;
            int gw = w0 - 1 + col;
            uint4 v = make_uint4(0,0,0,0);
            if (z >= 0 && z < DD && gh >= 0 && gh < HH && gw >= 0 && gw < WW)
                v = *(const uint4*)(xin + ((size_t)(z*HH + gh)*WW + gw)*4);
            *(uint4*)(slab + s*SLICEU + (row*18 + col)*4) = v;
        }
    }
    __syncthreads();

    float acc[DS][4];
    #pragma unroll
    for (int o = 0; o < DS; ++o)
        #pragma unroll
        for (int j = 0; j < 4; ++j) acc[o][j] = 0.f;

    #pragma unroll 1
    for (int kh = 0; kh < 3; ++kh) {
        #pragma unroll
        for (int kw = 0; kw < 3; ++kw) {
            const int p_lo = (ty + kh)*18 + kw + gid;
            const unsigned* plo = slab + p_lo*4 + tig;
            const unsigned* phi = plo + 32;
            unsigned alo[NSL], ahi[NSL];
            #pragma unroll
            for (int s = 0; s < NSL; ++s) {
                alo[s] = plo[s*SLICEU];
                ahi[s] = phi[s*SLICEU];
            }
            const unsigned* wb = s_w + (kh*3 + kw)*96;
            unsigned b0 = wb[tig*8 + gid];
            unsigned b1 = wb[32 + tig*8 + gid];
            unsigned b2 = wb[64 + tig*8 + gid];
            unsigned b01[2] = {b0, b1};
            #pragma unroll
            for (int o = 0; o < DS; ++o) {
                unsigned a16[4] = {alo[o], ahi[o], alo[o+1], ahi[o+1]};
                mma_f16_k16(acc[o], a16, b01);
                unsigned a8[2] = {alo[o+2], ahi[o+2]};
                mma_f16_k8(acc[o], a8, b2);
            }
        }
    }

    if (STAGE == 1) {
        const float b0f = bias[2*tig], b1f = bias[2*tig+1];
        #pragma unroll
        for (int o = 0; o < DS; ++o) {
            int d = d0 + o;
            unsigned* rowp = g_h1u + ((size_t)(d*HH + h0+ty)*WW + w0)*4 + tig;
            unsigned v0 = f22u(fmaxf(acc[o][0] + b0f, 0.f), fmaxf(acc[o][1] + b1f, 0.f));
            unsigned v1 = f22u(fmaxf(acc[o][2] + b0f, 0.f), fmaxf(acc[o][3] + b1f, 0.f));
            rowp[gid*4]     = v0;
            rowp[(gid+8)*4] = v1;
        }
    } else {
        const float b0f = bias[0];
        if (tig == 0) {
            #pragma unroll
            for (int o = 0; o < DS; ++o) {
                int d = d0 + o;
                float* row = g_cost + (size_t)(d*HH + h0+ty)*WW + w0;
                row[gid]   = acc[o][0] + b0f;
                row[gid+8] = acc[o][2] + b0f;
            }
        }
    }
}

// ---------------------------------------------------------------------------
// Kernel 7: softmax over D + expected depth + 4-tap confidence
// ---------------------------------------------------------------------------
__global__ void k_softmax(const float* __restrict__ dvals, float* __restrict__ out) {
    int p = blockIdx.x*blockDim.x + threadIdx.x;
    if (p >= HW) return;
    float c[DD];
    float m = -1e30f;
    #pragma unroll
    for (int d = 0; d < DD; ++d) { c[d] = g_cost[(size_t)d*HW + p]; m = fmaxf(m, c[d]); }
    float S = 0.f;
    #pragma unroll
    for (int d = 0; d < DD; ++d) { c[d] = expf(c[d] - m); S += c[d]; }
    float inv = 1.0f / S;
    float depth = 0.f, fid = 0.f;
    #pragma unroll
    for (int d = 0; d < DD; ++d) {
        float pr = c[d] * inv;
        depth = fmaf(pr, dvals[(size_t)d*HW + p], depth);
        fid   = fmaf(pr, (float)d, fid);
    }
    int di = (int)fid;
    di = max(0, min(DD-1, di));
    float conf = 0.f;
    #pragma unroll
    for (int d = 0; d < DD; ++d)
        if (d >= di-1 && d <= di+2) conf += c[d] * inv;
    out[p]      = depth;
    out[HW + p] = conf;
}

// ---------------------------------------------------------------------------
// Launch
// ---------------------------------------------------------------------------
extern "C" void kernel_launch(void* const* d_in, const int* in_sizes, int n_in,
                              void* d_out, int out_size) {
    const float* features = (const float*)d_in[0];
    const float* proj     = (const float*)d_in[1];
    const float* dvals    = (const float*)d_in[2];
    const float* w0 = (const float*)d_in[3];
    const float* b0 = (const float*)d_in[4];
    const float* w1 = (const float*)d_in[5];
    const float* b1 = (const float*)d_in[6];
    const float* w2 = (const float*)d_in[7];
    const float* b2 = (const float*)d_in[8];
    float* out = (float*)d_out;

    const int smem0  = 8*2880*4;                 // 92160 B (slab only)
    const int smem12 = (864 + 8*720)*4;          // 26496 B
    cudaFuncSetAttribute(k_conv0,   cudaFuncAttributeMaxDynamicSharedMemorySize, smem0);
    cudaFuncSetAttribute(k_conv<1>, cudaFuncAttributeMaxDynamicSharedMemorySize, smem12);
    cudaFuncSetAttribute(k_conv<2>, cudaFuncAttributeMaxDynamicSharedMemorySize, smem12);

    k_prep<<<15, 256>>>(proj, w0);
    dim3 tgrid(HW/32, VV);
    k_transpose<<<tgrid, dim3(32, 8)>>>(features);
    dim3 wgrid(HW/32, 3);
    k_warpvar<<<wgrid, 256>>>(dvals);

    dim3 cgrid(WW/16, HH/8, DD/6);   // (10, 16, 8)
    k_conv0<<<cgrid, 256, smem0>>>(w0, b0);
    k_conv<1><<<cgrid, 256, smem12>>>(w1, b1);
    k_conv<2><<<cgrid, 256, smem12>>>(w2, b2);

    k_softmax<<<(HW + 255)/256, 256>>>(dvals, out);
}